// round 16
// baseline (speedup 1.0000x reference)
#include <cuda_runtime.h>
#include <cuda_bf16.h>
#include <math.h>
#include <stdint.h>

#define JN 25
#define SPT 10
#define NTHR 256

typedef unsigned int u32;
typedef unsigned long long u64;

// dynamic smem byte offsets (all vector-access bases 16B-aligned)
#define OFF_WF   0        // 44 frags * 32 lanes * 16B = 22528
#define OFF_A1   22528    // 2500
#define OFF_A23  25028    // 2500
#define OFF_A4   27528    // 2500 (ends 30028)
#define OFF_B1   30032    // 256
#define OFF_B23  30288    // 256
#define OFF_B4   30544    // 16
#define OFF_XP   30560    // 256*16 = 4096 (Q overlays: Xp dead after stage2, Q born stage6)
#define OFF_Q    OFF_XP
#define OFF_P    34656    // 256*144 = 36864 (ends 71520)
#define OFF_M    71520    // 256*144 = 36864 (ends 108384); X staging overlays M head
#define OFF_X    OFF_M    // X (4000B) read in stage1, M written in stage4 - disjoint lifetimes
#define SMEM_BYTES 108384

#define F2_BASE 0    // 8 frags  (K=16, N=64)
#define F3_BASE 8    // 16 frags (K=64, N=32)
#define F5_BASE 24   // 16 frags (K=32, N=64)
#define F6_BASE 40   // 4 frags  (K=64, N=8)
#define NFRAG 44

__device__ float g_A1s[JN*JN];
__device__ float g_A2s[JN*JN];
__device__ float g_A3s[JN*JN];
__device__ float g_A23[JN*JN];
__device__ float g_A4s[JN*JN];
__device__ float g_b23[64];
__device__ uint4 g_WF[NFRAG*32];

// ---------- helpers ----------
__device__ __forceinline__ u64 pk2(float v) { u64 r; asm("mov.b64 %0, {%1, %1};" : "=l"(r) : "f"(v)); return r; }
__device__ __forceinline__ void upk(u64 v, float& lo, float& hi) { asm("mov.b64 {%0, %1}, %2;" : "=f"(lo), "=f"(hi) : "l"(v)); }
__device__ __forceinline__ u64 ffma2(u64 a, u64 b, u64 c) { u64 d; asm("fma.rn.f32x2 %0, %1, %2, %3;" : "=l"(d) : "l"(a), "l"(b), "l"(c)); return d; }
__device__ __forceinline__ u32 pkbf(float a, float b) {
    __nv_bfloat162 v = __floats2bfloat162_rn(a, b);
    return *(u32*)&v;
}
__device__ __forceinline__ void sp(float v, float& h, float& l) {
    __nv_bfloat16 hb = __float2bfloat16(v);
    h = __bfloat162float(hb);
    l = v - h;
}
__device__ __forceinline__ void mma16816(float* d, u32 a0, u32 a1, u32 a2, u32 a3, u32 b0, u32 b1) {
    asm volatile("mma.sync.aligned.m16n8k16.row.col.f32.bf16.bf16.f32 "
        "{%0,%1,%2,%3}, {%4,%5,%6,%7}, {%8,%9}, {%0,%1,%2,%3};"
        : "+f"(d[0]), "+f"(d[1]), "+f"(d[2]), "+f"(d[3])
        : "r"(a0), "r"(a1), "r"(a2), "r"(a3), "r"(b0), "r"(b1));
}
// relu + bf16-split two D-frags (8 f32) into next-layer A-frags (hi, lo)
__device__ __forceinline__ void cvt_frag(const float* e03, const float* e47, u32* ah, u32* al) {
    float h[8], l[8];
    #pragma unroll
    for (int i = 0; i < 4; i++) { float v = fmaxf(e03[i], 0.f); sp(v, h[i], l[i]); }
    #pragma unroll
    for (int i = 0; i < 4; i++) { float v = fmaxf(e47[i], 0.f); sp(v, h[4+i], l[4+i]); }
    ah[0] = pkbf(h[0], h[1]); ah[1] = pkbf(h[2], h[3]); ah[2] = pkbf(h[4], h[5]); ah[3] = pkbf(h[6], h[7]);
    al[0] = pkbf(l[0], l[1]); al[1] = pkbf(l[2], l[3]); al[2] = pkbf(l[4], l[5]); al[3] = pkbf(l[6], l[7]);
}

// ---------- prep ----------
__global__ void prep_kernel(const float* __restrict__ A1, const float* __restrict__ A2,
                            const float* __restrict__ A3, const float* __restrict__ A4,
                            const float* __restrict__ W1, const float* __restrict__ W2,
                            const float* __restrict__ b2, const float* __restrict__ W3,
                            const float* __restrict__ b3, const float* __restrict__ W4)
{
    int t = threadIdx.x;
    if (t < 4*JN) {
        int m = t / JN, r = t % JN;
        const float* src = (m==0) ? A1 : (m==1) ? A2 : (m==2) ? A3 : A4;
        float*       dst = (m==0) ? g_A1s : (m==1) ? g_A2s : (m==2) ? g_A3s : g_A4s;
        float mx = -1e30f;
        for (int k = 0; k < JN; k++) mx = fmaxf(mx, src[r*JN+k]);
        float e[JN]; float s = 0.f;
        for (int k = 0; k < JN; k++) { e[k] = expf(src[r*JN+k] - mx); s += e[k]; }
        float inv = 1.f / s;
        for (int k = 0; k < JN; k++) dst[r*JN+k] = e[k] * inv;
    }
    if (t >= 128 && t < 192) {
        int d = t - 128;
        float acc = b3[d];
        for (int c = 0; c < 32; c++) acc = fmaf(b2[c], W3[c*64+d], acc);
        g_b23[d] = acc;
    }
    __syncthreads();
    for (int i = t; i < JN*JN; i += blockDim.x) {
        int r = i / JN, c = i % JN;
        float acc = 0.f;
        for (int k = 0; k < JN; k++) acc = fmaf(g_A3s[r*JN+k], g_A2s[k*JN+c], acc);
        g_A23[i] = acc;
    }
    // weight B-fragments: lane holds B[k][n] at k=16kt+2t4(+{0,1},+8), n=8nt+g
    for (int i = t; i < NFRAG*32; i += blockDim.x) {
        int lane = i & 31, f = i >> 5;
        int t4 = lane & 3, g = lane >> 2;
        int kt = 0, nt = 0, layer;
        if (f < 8)       { layer = 0; nt = f; }
        else if (f < 24) { layer = 1; int q = f - 8;  kt = q >> 2; nt = q & 3; }
        else if (f < 40) { layer = 2; int q = f - 24; kt = q >> 3; nt = q & 7; }
        else             { layer = 3; kt = f - 40; }
        int n = 8*nt + g;
        int kb = 16*kt + 2*t4;
        float v[4];
        #pragma unroll
        for (int u = 0; u < 4; u++) {
            int k = kb + (u & 1) + (u >> 1) * 8;
            float val;
            if (layer == 0)      val = (k < 3) ? W1[k*64 + n] : 0.f;
            else if (layer == 1) val = W2[k*32 + n];
            else if (layer == 2) val = W3[k*64 + n];
            else                 val = (n < 3) ? W4[k*3 + n] : 0.f;
            v[u] = val;
        }
        float h[4], l[4];
        #pragma unroll
        for (int u = 0; u < 4; u++) sp(v[u], h[u], l[u]);
        uint4 o;
        o.x = pkbf(h[0], h[1]); o.y = pkbf(h[2], h[3]);
        o.z = pkbf(l[0], l[1]); o.w = pkbf(l[2], l[3]);
        g_WF[i] = o;
    }
}

// ---------- main ----------
__global__ void __launch_bounds__(NTHR, 2) gcn_mma_kernel(
    const float* __restrict__ x,
    const float* __restrict__ b1g, const float* __restrict__ b4g,
    float* __restrict__ out, int S_total, int ntiles)
{
    extern __shared__ char smem[];
    const int t = threadIdx.x;
    const int wid = t >> 5;
    const int lane = t & 31;
    const int t4 = lane & 3;
    const int g = lane >> 2;
    const int rw = 32 * wid;

    const uint4* sWF = (const uint4*)(smem + OFF_WF);
    float* sA1  = (float*)(smem + OFF_A1);
    float* sA23 = (float*)(smem + OFF_A23);
    float* sA4  = (float*)(smem + OFF_A4);
    float* sB1  = (float*)(smem + OFF_B1);
    float* sB23 = (float*)(smem + OFF_B23);
    float* sB4  = (float*)(smem + OFF_B4);
    float* sX   = (float*)(smem + OFF_X);   // overlays M head (disjoint lifetime)
    float* sP   = (float*)(smem + OFF_P);
    float* sQ   = (float*)(smem + OFF_Q);
    u32*   XpU  = (u32*)(smem + OFF_XP);
    u32*   MU   = (u32*)(smem + OFF_M);

    // init constants
    for (int i = t; i < NFRAG*32; i += NTHR) ((uint4*)(smem + OFF_WF))[i] = g_WF[i];
    for (int i = t; i < JN*JN; i += NTHR) { sA1[i] = g_A1s[i]; sA23[i] = g_A23[i]; sA4[i] = g_A4s[i]; }
    for (int i = t; i < 64; i += NTHR) { sB1[i] = b1g[i]; sB23[i] = g_b23[i]; }
    if (t < 4) sB4[t] = (t < 3) ? b4g[t] : 0.f;
    for (int i = t; i < 1024; i += NTHR) XpU[i] = 0u;
    for (int i = t; i < 256*36; i += NTHR) MU[i] = 0u;
    __syncthreads();

    const int jj = t % 25;
    const int ss = t / 25;

    for (int tile = blockIdx.x; tile < ntiles; tile += gridDim.x) {
        const int s0 = tile * SPT;
        const int nS = min(SPT, S_total - s0);
        const int nR = nS * 25;
        const int nF = nS * 75;
        const bool vrow = (t < nR);

        // load X (padded rows of 4) into M-head overlay (prev-tile M dead: last
        // read was stage5, multiple __syncthreads since)
        const float* xg = x + (size_t)s0 * 75;
        for (int i = t; i < nF; i += NTHR) sX[(i/3)*4 + (i%3)] = xg[i];
        __syncthreads();

        // ---- stage1 (rows): X' = A1s @ X, split+pack to Xp ----
        if (vrow) {
            float x0 = 0.f, x1 = 0.f, x2 = 0.f;
            const float* arow = sA1 + jj*25;
            const float4* xs = (const float4*)sX + ss*25;
            #pragma unroll
            for (int k = 0; k < 25; k++) {
                float4 v = xs[k]; float a = arow[k];
                x0 = fmaf(a, v.x, x0); x1 = fmaf(a, v.y, x1); x2 = fmaf(a, v.z, x2);
            }
            float h0,l0,h1,l1,h2,l2;
            sp(x0,h0,l0); sp(x1,h1,l1); sp(x2,h2,l2);
            uint4 xp;
            xp.x = pkbf(h0, h1); xp.y = pkbf(h2, 0.f);
            xp.z = pkbf(l0, l1); xp.w = pkbf(l2, 0.f);
            ((uint4*)XpU)[t] = xp;
        } else {
            uint4 z; z.x = z.y = z.z = z.w = 0u;
            ((uint4*)XpU)[t] = z;   // dead rows re-zeroed (Q overlay dirties them)
        }
        __syncthreads();

        // ---- stage2+3 (frags): D3 = relu(X'@W1+b1) @ W2 ----
        float d3[2][4][4];
        {
            float d2[2][8][4];
            #pragma unroll
            for (int mt = 0; mt < 2; mt++)
                #pragma unroll
                for (int nt = 0; nt < 8; nt++)
                    #pragma unroll
                    for (int q = 0; q < 4; q++) d2[mt][nt][q] = 0.f;

            u32 xh0[2], xh1[2], xl0[2], xl1[2];
            #pragma unroll
            for (int mt = 0; mt < 2; mt++) {
                int rA = rw + 16*mt + g;
                xh0[mt] = (t4 < 2) ? XpU[rA*4 + t4]       : 0u;
                xh1[mt] = (t4 < 2) ? XpU[(rA+8)*4 + t4]   : 0u;
                xl0[mt] = (t4 < 2) ? XpU[rA*4 + 2 + t4]     : 0u;
                xl1[mt] = (t4 < 2) ? XpU[(rA+8)*4 + 2 + t4] : 0u;
            }
            #pragma unroll
            for (int nt = 0; nt < 8; nt++) {
                uint4 B = sWF[(F2_BASE + nt)*32 + lane];
                float2 bb = *(const float2*)(sB1 + 8*nt + 2*t4);
                #pragma unroll
                for (int mt = 0; mt < 2; mt++) {
                    mma16816(d2[mt][nt], xh0[mt], xh1[mt], 0u, 0u, B.x, B.y);
                    mma16816(d2[mt][nt], xh0[mt], xh1[mt], 0u, 0u, B.z, B.w);
                    mma16816(d2[mt][nt], xl0[mt], xl1[mt], 0u, 0u, B.x, B.y);
                    d2[mt][nt][0] += bb.x; d2[mt][nt][1] += bb.y;
                    d2[mt][nt][2] += bb.x; d2[mt][nt][3] += bb.y;
                }
            }
            #pragma unroll
            for (int mt = 0; mt < 2; mt++)
                #pragma unroll
                for (int nt = 0; nt < 4; nt++)
                    #pragma unroll
                    for (int q = 0; q < 4; q++) d3[mt][nt][q] = 0.f;
            #pragma unroll
            for (int kt = 0; kt < 4; kt++) {
                u32 ah[2][4], al[2][4];
                #pragma unroll
                for (int mt = 0; mt < 2; mt++)
                    cvt_frag(d2[mt][2*kt], d2[mt][2*kt+1], ah[mt], al[mt]);
                #pragma unroll
                for (int nt = 0; nt < 4; nt++) {
                    uint4 B = sWF[(F3_BASE + kt*4 + nt)*32 + lane];
                    #pragma unroll
                    for (int mt = 0; mt < 2; mt++) {
                        mma16816(d3[mt][nt], ah[mt][0], ah[mt][1], ah[mt][2], ah[mt][3], B.x, B.y);
                        mma16816(d3[mt][nt], ah[mt][0], ah[mt][1], ah[mt][2], ah[mt][3], B.z, B.w);
                        mma16816(d3[mt][nt], al[mt][0], al[mt][1], al[mt][2], al[mt][3], B.x, B.y);
                    }
                }
            }
        }
        // STS P (f32, row stride 36)
        #pragma unroll
        for (int mt = 0; mt < 2; mt++) {
            int rA = rw + 16*mt + g;
            #pragma unroll
            for (int nt = 0; nt < 4; nt++) {
                float2 v0; v0.x = d3[mt][nt][0]; v0.y = d3[mt][nt][1];
                float2 v1; v1.x = d3[mt][nt][2]; v1.y = d3[mt][nt][3];
                *(float2*)(sP + rA*36 + 8*nt + 2*t4) = v0;
                *(float2*)(sP + (rA+8)*36 + 8*nt + 2*t4) = v1;
            }
        }
        __syncthreads();

        // ---- stage4 (rows): M = A23 @ P, split+pack to M smem ----
        // (X overlay is dead: stage1 finished, ordered by the syncs above)
        if (vrow) {
            u64 macc[16];
            #pragma unroll
            for (int p = 0; p < 16; p++) macc[p] = 0ull;
            const float* arow = sA23 + jj*25;
            const float* pbase = sP + ss*25*36;
            #pragma unroll 5
            for (int k = 0; k < 25; k++) {
                u64 a = pk2(arow[k]);
                const ulonglong2* pr = (const ulonglong2*)(pbase + k*36);
                #pragma unroll
                for (int q = 0; q < 8; q++) {
                    ulonglong2 w = pr[q];
                    macc[2*q]   = ffma2(a, w.x, macc[2*q]);
                    macc[2*q+1] = ffma2(a, w.y, macc[2*q+1]);
                }
            }
            u32* mrow = MU + t*36;
            #pragma unroll
            for (int p = 0; p < 16; p++) {
                float e0, e1; upk(macc[p], e0, e1);
                float h0, l0, h1, l1;
                sp(e0, h0, l0); sp(e1, h1, l1);
                mrow[p]      = pkbf(h0, h1);
                mrow[16 + p] = pkbf(l0, l1);
            }
        }
        __syncthreads();

        // ---- stage5 (frags): D5 = M @ W3 (+b23) ----
        float d5[2][8][4];
        #pragma unroll
        for (int mt = 0; mt < 2; mt++)
            #pragma unroll
            for (int nt = 0; nt < 8; nt++)
                #pragma unroll
                for (int q = 0; q < 4; q++) d5[mt][nt][q] = 0.f;
        #pragma unroll
        for (int kt = 0; kt < 2; kt++) {
            u32 ah[2][4], al[2][4];
            #pragma unroll
            for (int mt = 0; mt < 2; mt++) {
                int rA = rw + 16*mt + g;
                ah[mt][0] = MU[rA*36 + 8*kt + t4];
                ah[mt][1] = MU[(rA+8)*36 + 8*kt + t4];
                ah[mt][2] = MU[rA*36 + 8*kt + 4 + t4];
                ah[mt][3] = MU[(rA+8)*36 + 8*kt + 4 + t4];
                al[mt][0] = MU[rA*36 + 16 + 8*kt + t4];
                al[mt][1] = MU[(rA+8)*36 + 16 + 8*kt + t4];
                al[mt][2] = MU[rA*36 + 16 + 8*kt + 4 + t4];
                al[mt][3] = MU[(rA+8)*36 + 16 + 8*kt + 4 + t4];
            }
            #pragma unroll
            for (int nt = 0; nt < 8; nt++) {
                uint4 B = sWF[(F5_BASE + kt*8 + nt)*32 + lane];
                #pragma unroll
                for (int mt = 0; mt < 2; mt++) {
                    mma16816(d5[mt][nt], ah[mt][0], ah[mt][1], ah[mt][2], ah[mt][3], B.x, B.y);
                    mma16816(d5[mt][nt], ah[mt][0], ah[mt][1], ah[mt][2], ah[mt][3], B.z, B.w);
                    mma16816(d5[mt][nt], al[mt][0], al[mt][1], al[mt][2], al[mt][3], B.x, B.y);
                }
            }
        }
        #pragma unroll
        for (int nt = 0; nt < 8; nt++) {
            float2 bb = *(const float2*)(sB23 + 8*nt + 2*t4);
            #pragma unroll
            for (int mt = 0; mt < 2; mt++) {
                d5[mt][nt][0] += bb.x; d5[mt][nt][1] += bb.y;
                d5[mt][nt][2] += bb.x; d5[mt][nt][3] += bb.y;
            }
        }

        // ---- stage6 (frags): D6 = relu(D5) @ W4 ----
        float d6[2][4];
        #pragma unroll
        for (int mt = 0; mt < 2; mt++)
            #pragma unroll
            for (int q = 0; q < 4; q++) d6[mt][q] = 0.f;
        #pragma unroll
        for (int kt = 0; kt < 4; kt++) {
            uint4 B = sWF[(F6_BASE + kt)*32 + lane];
            #pragma unroll
            for (int mt = 0; mt < 2; mt++) {
                u32 ah[4], al[4];
                cvt_frag(d5[mt][2*kt], d5[mt][2*kt+1], ah, al);
                mma16816(d6[mt], ah[0], ah[1], ah[2], ah[3], B.x, B.y);
                mma16816(d6[mt], ah[0], ah[1], ah[2], ah[3], B.z, B.w);
                mma16816(d6[mt], al[0], al[1], al[2], al[3], B.x, B.y);
            }
        }
        // STS Q overlay (ordered after all Xp reads by the post-stage2/4 syncs)
        if (t4 < 2) {
            #pragma unroll
            for (int mt = 0; mt < 2; mt++) {
                int rA = rw + 16*mt + g;
                float2 v0; v0.x = d6[mt][0]; v0.y = d6[mt][1];
                float2 v1; v1.x = d6[mt][2]; v1.y = d6[mt][3];
                *(float2*)(sQ + rA*4 + 2*t4) = v0;
                *(float2*)(sQ + (rA+8)*4 + 2*t4) = v1;
            }
        }
        __syncthreads();

        // ---- stage7 (rows): out = A4s @ Q + b4 ----
        if (vrow) {
            float o0 = sB4[0], o1 = sB4[1], o2 = sB4[2];
            const float* arow = sA4 + jj*25;
            const float4* qs = (const float4*)sQ + ss*25;
            #pragma unroll
            for (int k = 0; k < 25; k++) {
                float4 qv = qs[k]; float a = arow[k];
                o0 = fmaf(a, qv.x, o0); o1 = fmaf(a, qv.y, o1); o2 = fmaf(a, qv.z, o2);
            }
            float* og = out + (size_t)s0 * 75 + t*3;
            og[0] = o0; og[1] = o1; og[2] = o2;
        }
        __syncthreads();
    }
}

extern "C" void kernel_launch(void* const* d_in, const int* in_sizes, int n_in,
                              void* d_out, int out_size)
{
    const float* x  = (const float*)d_in[0];
    const float* A1 = (const float*)d_in[1];
    const float* W1 = (const float*)d_in[2];
    const float* b1 = (const float*)d_in[3];
    const float* A2 = (const float*)d_in[4];
    const float* W2 = (const float*)d_in[5];
    const float* b2 = (const float*)d_in[6];
    const float* A3 = (const float*)d_in[7];
    const float* W3 = (const float*)d_in[8];
    const float* b3 = (const float*)d_in[9];
    const float* A4 = (const float*)d_in[10];
    const float* W4 = (const float*)d_in[11];
    const float* b4 = (const float*)d_in[12];
    float* out = (float*)d_out;

    const int S_total = in_sizes[0] / 75;
    const int ntiles = (S_total + SPT - 1) / SPT;

    cudaFuncSetAttribute(gcn_mma_kernel, cudaFuncAttributeMaxDynamicSharedMemorySize, SMEM_BYTES);

    prep_kernel<<<1, 256>>>(A1, A2, A3, A4, W1, W2, b2, W3, b3, W4);

    int grid = ntiles < 296 ? ntiles : 296;   // 2 CTAs/SM x 148
    gcn_mma_kernel<<<grid, NTHR, SMEM_BYTES>>>(x, b1, b4, out, S_total, ntiles);
}

// round 17
// speedup vs baseline: 1.1697x; 1.1697x over previous
#include <cuda_runtime.h>
#include <cuda_bf16.h>
#include <math.h>
#include <stdint.h>

#define JN 25
#define SPT 5
#define NTHR 128

typedef unsigned int u32;
typedef unsigned long long u64;

// dynamic smem byte offsets (all vector-access bases 16B-aligned)
#define OFF_WF   0        // 44 frags * 32 lanes * 16B = 22528
#define OFF_A1   22528    // 2500
#define OFF_A23  25028    // 2500
#define OFF_A4   27528    // 2500 (ends 30028)
#define OFF_B1   30032    // 256
#define OFF_B23  30288    // 256
#define OFF_B4   30544    // 16
#define OFF_XP   30560    // 128*16 = 2048 (Q overlays: Xp dead after stage2, Q born stage6)
#define OFF_Q    OFF_XP
#define OFF_X    32608    // 125*16 = 2000 (+pad)
#define OFF_P    34624    // 128*144 = 18432 (ends 53056)
#define OFF_M    OFF_P    // M overlays P: P-reads complete (reg-held macc) before M-writes, sync-separated
#define SMEM_BYTES 53056  // x4 CTAs = 212KB <= 228KB

#define F2_BASE 0    // 8 frags  (K=16, N=64)
#define F3_BASE 8    // 16 frags (K=64, N=32)
#define F5_BASE 24   // 16 frags (K=32, N=64)
#define F6_BASE 40   // 4 frags  (K=64, N=8)
#define NFRAG 44

__device__ float g_A1s[JN*JN];
__device__ float g_A2s[JN*JN];
__device__ float g_A3s[JN*JN];
__device__ float g_A23[JN*JN];
__device__ float g_A4s[JN*JN];
__device__ float g_b23[64];
__device__ uint4 g_WF[NFRAG*32];

// ---------- helpers ----------
__device__ __forceinline__ u64 pk2(float v) { u64 r; asm("mov.b64 %0, {%1, %1};" : "=l"(r) : "f"(v)); return r; }
__device__ __forceinline__ void upk(u64 v, float& lo, float& hi) { asm("mov.b64 {%0, %1}, %2;" : "=f"(lo), "=f"(hi) : "l"(v)); }
__device__ __forceinline__ u64 ffma2(u64 a, u64 b, u64 c) { u64 d; asm("fma.rn.f32x2 %0, %1, %2, %3;" : "=l"(d) : "l"(a), "l"(b), "l"(c)); return d; }
__device__ __forceinline__ u32 pkbf(float a, float b) {
    __nv_bfloat162 v = __floats2bfloat162_rn(a, b);
    return *(u32*)&v;
}
__device__ __forceinline__ void sp(float v, float& h, float& l) {
    __nv_bfloat16 hb = __float2bfloat16(v);
    h = __bfloat162float(hb);
    l = v - h;
}
__device__ __forceinline__ void mma16816(float* d, u32 a0, u32 a1, u32 a2, u32 a3, u32 b0, u32 b1) {
    asm volatile("mma.sync.aligned.m16n8k16.row.col.f32.bf16.bf16.f32 "
        "{%0,%1,%2,%3}, {%4,%5,%6,%7}, {%8,%9}, {%0,%1,%2,%3};"
        : "+f"(d[0]), "+f"(d[1]), "+f"(d[2]), "+f"(d[3])
        : "r"(a0), "r"(a1), "r"(a2), "r"(a3), "r"(b0), "r"(b1));
}
// relu + bf16-split two D-frags (8 f32) into next-layer A-frags (hi, lo)
__device__ __forceinline__ void cvt_frag(const float* e03, const float* e47, u32* ah, u32* al) {
    float h[8], l[8];
    #pragma unroll
    for (int i = 0; i < 4; i++) { float v = fmaxf(e03[i], 0.f); sp(v, h[i], l[i]); }
    #pragma unroll
    for (int i = 0; i < 4; i++) { float v = fmaxf(e47[i], 0.f); sp(v, h[4+i], l[4+i]); }
    ah[0] = pkbf(h[0], h[1]); ah[1] = pkbf(h[2], h[3]); ah[2] = pkbf(h[4], h[5]); ah[3] = pkbf(h[6], h[7]);
    al[0] = pkbf(l[0], l[1]); al[1] = pkbf(l[2], l[3]); al[2] = pkbf(l[4], l[5]); al[3] = pkbf(l[6], l[7]);
}

// ---------- prep ----------
__global__ void prep_kernel(const float* __restrict__ A1, const float* __restrict__ A2,
                            const float* __restrict__ A3, const float* __restrict__ A4,
                            const float* __restrict__ W1, const float* __restrict__ W2,
                            const float* __restrict__ b2, const float* __restrict__ W3,
                            const float* __restrict__ b3, const float* __restrict__ W4)
{
    int t = threadIdx.x;
    if (t < 4*JN) {
        int m = t / JN, r = t % JN;
        const float* src = (m==0) ? A1 : (m==1) ? A2 : (m==2) ? A3 : A4;
        float*       dst = (m==0) ? g_A1s : (m==1) ? g_A2s : (m==2) ? g_A3s : g_A4s;
        float mx = -1e30f;
        for (int k = 0; k < JN; k++) mx = fmaxf(mx, src[r*JN+k]);
        float e[JN]; float s = 0.f;
        for (int k = 0; k < JN; k++) { e[k] = expf(src[r*JN+k] - mx); s += e[k]; }
        float inv = 1.f / s;
        for (int k = 0; k < JN; k++) dst[r*JN+k] = e[k] * inv;
    }
    if (t >= 128 && t < 192) {
        int d = t - 128;
        float acc = b3[d];
        for (int c = 0; c < 32; c++) acc = fmaf(b2[c], W3[c*64+d], acc);
        g_b23[d] = acc;
    }
    __syncthreads();
    for (int i = t; i < JN*JN; i += blockDim.x) {
        int r = i / JN, c = i % JN;
        float acc = 0.f;
        for (int k = 0; k < JN; k++) acc = fmaf(g_A3s[r*JN+k], g_A2s[k*JN+c], acc);
        g_A23[i] = acc;
    }
    // weight B-fragments: lane holds B[k][n] at k=16kt+2t4(+{0,1},+8), n=8nt+g
    for (int i = t; i < NFRAG*32; i += blockDim.x) {
        int lane = i & 31, f = i >> 5;
        int t4 = lane & 3, g = lane >> 2;
        int kt = 0, nt = 0, layer;
        if (f < 8)       { layer = 0; nt = f; }
        else if (f < 24) { layer = 1; int q = f - 8;  kt = q >> 2; nt = q & 3; }
        else if (f < 40) { layer = 2; int q = f - 24; kt = q >> 3; nt = q & 7; }
        else             { layer = 3; kt = f - 40; }
        int n = 8*nt + g;
        int kb = 16*kt + 2*t4;
        float v[4];
        #pragma unroll
        for (int u = 0; u < 4; u++) {
            int k = kb + (u & 1) + (u >> 1) * 8;
            float val;
            if (layer == 0)      val = (k < 3) ? W1[k*64 + n] : 0.f;
            else if (layer == 1) val = W2[k*32 + n];
            else if (layer == 2) val = W3[k*64 + n];
            else                 val = (n < 3) ? W4[k*3 + n] : 0.f;
            v[u] = val;
        }
        float h[4], l[4];
        #pragma unroll
        for (int u = 0; u < 4; u++) sp(v[u], h[u], l[u]);
        uint4 o;
        o.x = pkbf(h[0], h[1]); o.y = pkbf(h[2], h[3]);
        o.z = pkbf(l[0], l[1]); o.w = pkbf(l[2], l[3]);
        g_WF[i] = o;
    }
}

// ---------- main ----------
__global__ void __launch_bounds__(NTHR, 4) gcn_mma_kernel(
    const float* __restrict__ x,
    const float* __restrict__ b1g, const float* __restrict__ b4g,
    float* __restrict__ out, int S_total, int ntiles)
{
    extern __shared__ char smem[];
    const int t = threadIdx.x;
    const int wid = t >> 5;
    const int lane = t & 31;
    const int t4 = lane & 3;
    const int g = lane >> 2;
    const int rw = 32 * wid;

    const uint4* sWF = (const uint4*)(smem + OFF_WF);
    float* sA1  = (float*)(smem + OFF_A1);
    float* sA23 = (float*)(smem + OFF_A23);
    float* sA4  = (float*)(smem + OFF_A4);
    float* sB1  = (float*)(smem + OFF_B1);
    float* sB23 = (float*)(smem + OFF_B23);
    float* sB4  = (float*)(smem + OFF_B4);
    float* sX   = (float*)(smem + OFF_X);
    float* sP   = (float*)(smem + OFF_P);
    float* sQ   = (float*)(smem + OFF_Q);
    u32*   XpU  = (u32*)(smem + OFF_XP);
    u32*   MU   = (u32*)(smem + OFF_M);   // overlays P

    // init constants
    for (int i = t; i < NFRAG*32; i += NTHR) ((uint4*)(smem + OFF_WF))[i] = g_WF[i];
    for (int i = t; i < JN*JN; i += NTHR) { sA1[i] = g_A1s[i]; sA23[i] = g_A23[i]; sA4[i] = g_A4s[i]; }
    for (int i = t; i < 64; i += NTHR) { sB1[i] = b1g[i]; sB23[i] = g_b23[i]; }
    if (t < 4) sB4[t] = (t < 3) ? b4g[t] : 0.f;
    for (int i = t; i < 512; i += NTHR) XpU[i] = 0u;
    __syncthreads();

    const int jj = t % 25;
    const int ss = t / 25;

    for (int tile = blockIdx.x; tile < ntiles; tile += gridDim.x) {
        const int s0 = tile * SPT;
        const int nS = min(SPT, S_total - s0);
        const int nR = nS * 25;
        const int nF = nS * 75;
        const bool vrow = (t < nR);

        // load X (padded rows of 4)
        const float* xg = x + (size_t)s0 * 75;
        for (int i = t; i < nF; i += NTHR) sX[(i/3)*4 + (i%3)] = xg[i];
        __syncthreads();

        // ---- stage1 (rows): X' = A1s @ X, split+pack to Xp ----
        if (vrow) {
            float x0 = 0.f, x1 = 0.f, x2 = 0.f;
            const float* arow = sA1 + jj*25;
            const float4* xs = (const float4*)sX + ss*25;
            #pragma unroll
            for (int k = 0; k < 25; k++) {
                float4 v = xs[k]; float a = arow[k];
                x0 = fmaf(a, v.x, x0); x1 = fmaf(a, v.y, x1); x2 = fmaf(a, v.z, x2);
            }
            float h0,l0,h1,l1,h2,l2;
            sp(x0,h0,l0); sp(x1,h1,l1); sp(x2,h2,l2);
            uint4 xp;
            xp.x = pkbf(h0, h1); xp.y = pkbf(h2, 0.f);
            xp.z = pkbf(l0, l1); xp.w = pkbf(l2, 0.f);
            ((uint4*)XpU)[t] = xp;
        } else {
            uint4 z; z.x = z.y = z.z = z.w = 0u;
            ((uint4*)XpU)[t] = z;   // dead rows re-zeroed (Q overlay dirties them)
        }
        __syncthreads();

        // ---- stage2+3 (frags): D3 = relu(X'@W1+b1) @ W2 ----
        float d3[2][4][4];
        {
            float d2[2][8][4];
            #pragma unroll
            for (int mt = 0; mt < 2; mt++)
                #pragma unroll
                for (int nt = 0; nt < 8; nt++)
                    #pragma unroll
                    for (int q = 0; q < 4; q++) d2[mt][nt][q] = 0.f;

            u32 xh0[2], xh1[2], xl0[2], xl1[2];
            #pragma unroll
            for (int mt = 0; mt < 2; mt++) {
                int rA = rw + 16*mt + g;
                xh0[mt] = (t4 < 2) ? XpU[rA*4 + t4]       : 0u;
                xh1[mt] = (t4 < 2) ? XpU[(rA+8)*4 + t4]   : 0u;
                xl0[mt] = (t4 < 2) ? XpU[rA*4 + 2 + t4]     : 0u;
                xl1[mt] = (t4 < 2) ? XpU[(rA+8)*4 + 2 + t4] : 0u;
            }
            #pragma unroll
            for (int nt = 0; nt < 8; nt++) {
                uint4 B = sWF[(F2_BASE + nt)*32 + lane];
                float2 bb = *(const float2*)(sB1 + 8*nt + 2*t4);
                #pragma unroll
                for (int mt = 0; mt < 2; mt++) {
                    mma16816(d2[mt][nt], xh0[mt], xh1[mt], 0u, 0u, B.x, B.y);
                    mma16816(d2[mt][nt], xh0[mt], xh1[mt], 0u, 0u, B.z, B.w);
                    mma16816(d2[mt][nt], xl0[mt], xl1[mt], 0u, 0u, B.x, B.y);
                    d2[mt][nt][0] += bb.x; d2[mt][nt][1] += bb.y;
                    d2[mt][nt][2] += bb.x; d2[mt][nt][3] += bb.y;
                }
            }
            #pragma unroll
            for (int mt = 0; mt < 2; mt++)
                #pragma unroll
                for (int nt = 0; nt < 4; nt++)
                    #pragma unroll
                    for (int q = 0; q < 4; q++) d3[mt][nt][q] = 0.f;
            #pragma unroll
            for (int kt = 0; kt < 4; kt++) {
                u32 ah[2][4], al[2][4];
                #pragma unroll
                for (int mt = 0; mt < 2; mt++)
                    cvt_frag(d2[mt][2*kt], d2[mt][2*kt+1], ah[mt], al[mt]);
                #pragma unroll
                for (int nt = 0; nt < 4; nt++) {
                    uint4 B = sWF[(F3_BASE + kt*4 + nt)*32 + lane];
                    #pragma unroll
                    for (int mt = 0; mt < 2; mt++) {
                        mma16816(d3[mt][nt], ah[mt][0], ah[mt][1], ah[mt][2], ah[mt][3], B.x, B.y);
                        mma16816(d3[mt][nt], ah[mt][0], ah[mt][1], ah[mt][2], ah[mt][3], B.z, B.w);
                        mma16816(d3[mt][nt], al[mt][0], al[mt][1], al[mt][2], al[mt][3], B.x, B.y);
                    }
                }
            }
        }
        // STS P (f32, row stride 36)
        #pragma unroll
        for (int mt = 0; mt < 2; mt++) {
            int rA = rw + 16*mt + g;
            #pragma unroll
            for (int nt = 0; nt < 4; nt++) {
                float2 v0; v0.x = d3[mt][nt][0]; v0.y = d3[mt][nt][1];
                float2 v1; v1.x = d3[mt][nt][2]; v1.y = d3[mt][nt][3];
                *(float2*)(sP + rA*36 + 8*nt + 2*t4) = v0;
                *(float2*)(sP + (rA+8)*36 + 8*nt + 2*t4) = v1;
            }
        }
        __syncthreads();

        // ---- stage4 (rows): M = A23 @ P into registers ----
        u64 macc[16];
        #pragma unroll
        for (int p = 0; p < 16; p++) macc[p] = 0ull;
        if (vrow) {
            const float* arow = sA23 + jj*25;
            const float* pbase = sP + ss*25*36;
            #pragma unroll 5
            for (int k = 0; k < 25; k++) {
                u64 a = pk2(arow[k]);
                const ulonglong2* pr = (const ulonglong2*)(pbase + k*36);
                #pragma unroll
                for (int q = 0; q < 8; q++) {
                    ulonglong2 w = pr[q];
                    macc[2*q]   = ffma2(a, w.x, macc[2*q]);
                    macc[2*q+1] = ffma2(a, w.y, macc[2*q+1]);
                }
            }
        }
        __syncthreads();   // ALL P reads done before M overlay writes

        if (vrow) {
            u32* mrow = MU + t*36;
            #pragma unroll
            for (int p = 0; p < 16; p++) {
                float e0, e1; upk(macc[p], e0, e1);
                float h0, l0, h1, l1;
                sp(e0, h0, l0); sp(e1, h1, l1);
                mrow[p]      = pkbf(h0, h1);
                mrow[16 + p] = pkbf(l0, l1);
            }
        }
        __syncthreads();

        // ---- stage5 (frags): D5 = M @ W3 (+b23) ----
        // (dead M rows hold stale P bits: garbage is row-confined in MMA,
        //  flows only to dead D rows, never read by valid threads)
        float d5[2][8][4];
        #pragma unroll
        for (int mt = 0; mt < 2; mt++)
            #pragma unroll
            for (int nt = 0; nt < 8; nt++)
                #pragma unroll
                for (int q = 0; q < 4; q++) d5[mt][nt][q] = 0.f;
        #pragma unroll
        for (int kt = 0; kt < 2; kt++) {
            u32 ah[2][4], al[2][4];
            #pragma unroll
            for (int mt = 0; mt < 2; mt++) {
                int rA = rw + 16*mt + g;
                ah[mt][0] = MU[rA*36 + 8*kt + t4];
                ah[mt][1] = MU[(rA+8)*36 + 8*kt + t4];
                ah[mt][2] = MU[rA*36 + 8*kt + 4 + t4];
                ah[mt][3] = MU[(rA+8)*36 + 8*kt + 4 + t4];
                al[mt][0] = MU[rA*36 + 16 + 8*kt + t4];
                al[mt][1] = MU[(rA+8)*36 + 16 + 8*kt + t4];
                al[mt][2] = MU[rA*36 + 16 + 8*kt + 4 + t4];
                al[mt][3] = MU[(rA+8)*36 + 16 + 8*kt + 4 + t4];
            }
            #pragma unroll
            for (int nt = 0; nt < 8; nt++) {
                uint4 B = sWF[(F5_BASE + kt*8 + nt)*32 + lane];
                #pragma unroll
                for (int mt = 0; mt < 2; mt++) {
                    mma16816(d5[mt][nt], ah[mt][0], ah[mt][1], ah[mt][2], ah[mt][3], B.x, B.y);
                    mma16816(d5[mt][nt], ah[mt][0], ah[mt][1], ah[mt][2], ah[mt][3], B.z, B.w);
                    mma16816(d5[mt][nt], al[mt][0], al[mt][1], al[mt][2], al[mt][3], B.x, B.y);
                }
            }
        }
        #pragma unroll
        for (int nt = 0; nt < 8; nt++) {
            float2 bb = *(const float2*)(sB23 + 8*nt + 2*t4);
            #pragma unroll
            for (int mt = 0; mt < 2; mt++) {
                d5[mt][nt][0] += bb.x; d5[mt][nt][1] += bb.y;
                d5[mt][nt][2] += bb.x; d5[mt][nt][3] += bb.y;
            }
        }

        // ---- stage6 (frags): D6 = relu(D5) @ W4 ----
        float d6[2][4];
        #pragma unroll
        for (int mt = 0; mt < 2; mt++)
            #pragma unroll
            for (int q = 0; q < 4; q++) d6[mt][q] = 0.f;
        #pragma unroll
        for (int kt = 0; kt < 4; kt++) {
            uint4 B = sWF[(F6_BASE + kt)*32 + lane];
            #pragma unroll
            for (int mt = 0; mt < 2; mt++) {
                u32 ah[4], al[4];
                cvt_frag(d5[mt][2*kt], d5[mt][2*kt+1], ah, al);
                mma16816(d6[mt], ah[0], ah[1], ah[2], ah[3], B.x, B.y);
                mma16816(d6[mt], ah[0], ah[1], ah[2], ah[3], B.z, B.w);
                mma16816(d6[mt], al[0], al[1], al[2], al[3], B.x, B.y);
            }
        }
        // STS Q overlay (ordered after all Xp reads by the post-stage2/4 syncs)
        if (t4 < 2) {
            #pragma unroll
            for (int mt = 0; mt < 2; mt++) {
                int rA = rw + 16*mt + g;
                float2 v0; v0.x = d6[mt][0]; v0.y = d6[mt][1];
                float2 v1; v1.x = d6[mt][2]; v1.y = d6[mt][3];
                *(float2*)(sQ + rA*4 + 2*t4) = v0;
                *(float2*)(sQ + (rA+8)*4 + 2*t4) = v1;
            }
        }
        __syncthreads();

        // ---- stage7 (rows): out = A4s @ Q + b4 ----
        if (vrow) {
            float o0 = sB4[0], o1 = sB4[1], o2 = sB4[2];
            const float* arow = sA4 + jj*25;
            const float4* qs = (const float4*)sQ + ss*25;
            #pragma unroll
            for (int k = 0; k < 25; k++) {
                float4 qv = qs[k]; float a = arow[k];
                o0 = fmaf(a, qv.x, o0); o1 = fmaf(a, qv.y, o1); o2 = fmaf(a, qv.z, o2);
            }
            float* og = out + (size_t)s0 * 75 + t*3;
            og[0] = o0; og[1] = o1; og[2] = o2;
        }
        __syncthreads();
    }
}

extern "C" void kernel_launch(void* const* d_in, const int* in_sizes, int n_in,
                              void* d_out, int out_size)
{
    const float* x  = (const float*)d_in[0];
    const float* A1 = (const float*)d_in[1];
    const float* W1 = (const float*)d_in[2];
    const float* b1 = (const float*)d_in[3];
    const float* A2 = (const float*)d_in[4];
    const float* W2 = (const float*)d_in[5];
    const float* b2 = (const float*)d_in[6];
    const float* A3 = (const float*)d_in[7];
    const float* W3 = (const float*)d_in[8];
    const float* b3 = (const float*)d_in[9];
    const float* A4 = (const float*)d_in[10];
    const float* W4 = (const float*)d_in[11];
    const float* b4 = (const float*)d_in[12];
    float* out = (float*)d_out;

    const int S_total = in_sizes[0] / 75;
    const int ntiles = (S_total + SPT - 1) / SPT;

    cudaFuncSetAttribute(gcn_mma_kernel, cudaFuncAttributeMaxDynamicSharedMemorySize, SMEM_BYTES);

    prep_kernel<<<1, 256>>>(A1, A2, A3, A4, W1, W2, b2, W3, b3, W4);

    int grid = ntiles < 592 ? ntiles : 592;   // 4 CTAs/SM x 148
    gcn_mma_kernel<<<grid, NTHR, SMEM_BYTES>>>(x, b1, b4, out, S_total, ntiles);
}